// round 14
// baseline (speedup 1.0000x reference)
#include <cuda_runtime.h>
#include <cuda_bf16.h>
#include <cstdint>

// Problem constants (fixed by reference setup_inputs)
#define BATCH 4096
#define CELL  400
#define CELL4 100    // CELL/4
#define KMIX  10
#define TLEN  256
#define VDIM  80
#define NT    320    // 10 warps == KMIX warps
#define GRID  912    // 6 CTAs x 152 SMs; over-provision safe (dynamic grabbing)

#define JPRE   5                    // prefetched 16-row chunks: t < 80
#define PRE_F4 (JPRE * 16 * 20)     // 1600 float4 = 25600 B

// persistent-scheduler state (self-resetting each launch for graph replay)
__device__ unsigned g_ctr  = 0;
__device__ unsigned g_done = 0;

#define CP_ASYNC_16(s, g) \
    asm volatile("cp.async.cg.shared.global [%0], [%1], 16;" :: "r"(s), "l"(g))
#define CP_COMMIT() asm volatile("cp.async.commit_group;" ::: "memory")
#define CP_WAIT0()  asm volatile("cp.async.wait_group 0;" ::: "memory")

__global__ __launch_bounds__(NT)
void window_persistent(const float* __restrict__ x,
                       const float* __restrict__ kappa_old,
                       const float* __restrict__ onehots,
                       const float* __restrict__ W,
                       const float* __restrict__ bias,
                       float* __restrict__ out_weight,   // [B, V]
                       float* __restrict__ out_kappa)    // [B, K]
{
    const int tid  = threadIdx.x;
    const int warp = tid >> 5;
    const int lane = tid & 31;
    const int c    = tid % 20;    // float4 column (v/4)
    const int t0   = tid / 20;    // 0..15

    __shared__ float4 soh[PRE_F4];     // 25.6KB: prefetched head of current job
    __shared__ float  sphi[2][TLEN];   // ping-pong phi
    __shared__ float4 wpart[16 * 20];
    __shared__ float  sabk[32];        // alpha[10] | beta[10] | kappa[10]
    __shared__ int    sjob;

    const uint32_t soh_u32 = (uint32_t)__cvta_generic_to_shared(soh);

    // ---- lambda-ish helpers as macros over locals ----
    #define ISSUE_PREFETCH(JOB)                                              \
        do {                                                                 \
            const float4* _g = (const float4*)(onehots + (size_t)(JOB) * TLEN * VDIM); \
            _Pragma("unroll")                                                \
            for (int _k = 0; _k < PRE_F4 / NT; _k++) {                       \
                const int _i = tid + _k * NT;                                \
                CP_ASYNC_16(soh_u32 + _i * 16, _g + _i);                     \
            }                                                                \
            CP_COMMIT();                                                     \
        } while (0)

    // prologue: mat-vec + transforms + phi for job JB into sphi[BUF].
    // Contains one __syncthreads — callers must invoke it uniformly.
    #define PROLOGUE(JB, BUF)                                                \
        do {                                                                 \
            const float4* _x4 = (const float4*)(x + (size_t)(JB) * CELL);    \
            const float4* _W4 = (const float4*)W;                            \
            float _s0 = 0.f, _s1 = 0.f, _s2 = 0.f;                           \
            _Pragma("unroll 4")                                              \
            for (int _c4 = lane; _c4 < CELL4; _c4 += 32) {                   \
                const float4 _xv = _x4[_c4];                                 \
                const float4 _w0 = _W4[(warp)          * CELL4 + _c4];       \
                const float4 _w1 = _W4[(warp + KMIX)   * CELL4 + _c4];       \
                const float4 _w2 = _W4[(warp + 2*KMIX) * CELL4 + _c4];       \
                _s0 += _xv.x*_w0.x + _xv.y*_w0.y + _xv.z*_w0.z + _xv.w*_w0.w;\
                _s1 += _xv.x*_w1.x + _xv.y*_w1.y + _xv.z*_w1.z + _xv.w*_w1.w;\
                _s2 += _xv.x*_w2.x + _xv.y*_w2.y + _xv.z*_w2.z + _xv.w*_w2.w;\
            }                                                                \
            _Pragma("unroll")                                                \
            for (int _o = 16; _o > 0; _o >>= 1) {                            \
                _s0 += __shfl_xor_sync(0xffffffffu, _s0, _o);                \
                _s1 += __shfl_xor_sync(0xffffffffu, _s1, _o);                \
                _s2 += __shfl_xor_sync(0xffffffffu, _s2, _o);                \
            }                                                                \
            if (lane == 0) {                                                 \
                const float _kap = kappa_old[(size_t)(JB) * KMIX + warp]     \
                                 + __expf(_s2 + bias[warp + 2*KMIX]);        \
                sabk[warp]          = __expf(_s0 + bias[warp]);              \
                sabk[warp + KMIX]   = __expf(_s1 + bias[warp + KMIX]);       \
                sabk[warp + 2*KMIX] = _kap;                                  \
                out_kappa[(size_t)(JB) * KMIX + warp] = _kap;                \
            }                                                                \
            __syncthreads();                                                 \
            if (tid < TLEN) {                                                \
                const float _u = (float)tid;                                 \
                float _s = 0.f;                                              \
                _Pragma("unroll")                                            \
                for (int _k = 0; _k < KMIX; _k++) {                          \
                    const float _d = sabk[2*KMIX + _k] - _u;                 \
                    _s += sabk[_k] * __expf(-sabk[KMIX + _k] * _d * _d);     \
                }                                                            \
                sphi[BUF][tid] = _s;                                         \
            }                                                                \
        } while (0)

    // ---- grab first job ----
    if (tid == 0) sjob = (int)atomicAdd(&g_ctr, 1u);
    __syncthreads();
    int j   = sjob;
    int cur = 0;

    if (j < BATCH) {
        ISSUE_PREFETCH(j);
        PROLOGUE(j, 0);
    }

    while (j < BATCH) {
        const float4* oh = (const float4*)(onehots + (size_t)j * TLEN * VDIM);

        CP_WAIT0();
        __syncthreads();   // soh + sphi[cur] visible; wpart free

        float4 acc = make_float4(0.f, 0.f, 0.f, 0.f);
        // head: t < 80 from smem
        #pragma unroll
        for (int m = 0; m < JPRE; m++) {
            const int t = t0 + m * 16;
            const float  p = sphi[cur][t];
            const float4 o = soh[t * 20 + c];
            acc.x += p * o.x; acc.y += p * o.y; acc.z += p * o.z; acc.w += p * o.w;
        }

        if (tid == 0) sjob = (int)atomicAdd(&g_ctr, 1u);
        __syncthreads();   // soh free to refill; sjob visible
        const int jn = sjob;

        // keep the slot's DRAM queue non-empty: next job's head queued
        // behind this job's tail loads
        if (jn < BATCH) ISSUE_PREFETCH(jn);

        // tail: t >= 80 plain LDG
        #pragma unroll
        for (int m = JPRE; m < 16; m++) {
            const int t = t0 + m * 16;
            const float  p = sphi[cur][t];
            const float4 o = oh[t * 20 + c];
            acc.x += p * o.x; acc.y += p * o.y; acc.z += p * o.z; acc.w += p * o.w;
        }

        // next job's prologue runs while its prefetch drains
        if (jn < BATCH) PROLOGUE(jn, cur ^ 1);

        wpart[t0 * 20 + c] = acc;
        __syncthreads();
        if (tid < VDIM) {
            const float* wp = (const float*)wpart;
            float s = 0.f;
            #pragma unroll
            for (int q = 0; q < 16; q++) s += wp[q * VDIM + tid];
            out_weight[(size_t)j * VDIM + tid] = s;
        }

        j = jn;
        cur ^= 1;
    }

    // ---- self-reset scheduler state (deterministic across graph replays) ----
    __syncthreads();
    if (tid == 0) {
        if (atomicAdd(&g_done, 1u) == GRID - 1) {
            g_ctr  = 0;
            g_done = 0;
            __threadfence();
        }
    }
    #undef ISSUE_PREFETCH
    #undef PROLOGUE
}

extern "C" void kernel_launch(void* const* d_in, const int* in_sizes, int n_in,
                              void* d_out, int out_size)
{
    const float* x         = (const float*)d_in[0];   // [B, CELL]
    const float* kappa_old = (const float*)d_in[1];   // [B, K]
    const float* onehots   = (const float*)d_in[2];   // [B, T, V]
    const float* W         = (const float*)d_in[3];   // [3K, CELL]
    const float* bias      = (const float*)d_in[4];   // [3K]

    float* out_weight = (float*)d_out;                        // [B, V]
    float* out_kappa  = (float*)d_out + (size_t)BATCH * VDIM; // [B, K]

    window_persistent<<<GRID, NT>>>(x, kappa_old, onehots, W, bias,
                                    out_weight, out_kappa);
}